// round 16
// baseline (speedup 1.0000x reference)
#include <cuda_runtime.h>
#include <cstdint>

#define NB 8
#define NN 2048
#define DD 128

// Scratch (static device globals — no runtime allocation)
__device__ float g_hn[NB * NN * DD];   // normalized h, row-major [B][N][D]
__device__ float g_ht[NB * DD * NN];   // h (unnormalized), TRANSPOSED [B][D][N]

__device__ __forceinline__ float to_tf32(float x) {
    float r;
    asm("cvt.rna.tf32.f32 %0, %1;" : "=f"(r) : "f"(x));
    return r;
}
__device__ __forceinline__ unsigned fbits(float x) { return __float_as_uint(x); }

// D += A(16x8, tf32 row) * B(8x8, tf32 col), fp32 accumulate
__device__ __forceinline__ void mma8(float c[4], const unsigned a[4], unsigned b0, unsigned b1) {
    asm volatile(
        "mma.sync.aligned.m16n8k8.row.col.f32.tf32.tf32.f32 "
        "{%0,%1,%2,%3}, {%4,%5,%6,%7}, {%8,%9}, {%0,%1,%2,%3};\n"
        : "+f"(c[0]), "+f"(c[1]), "+f"(c[2]), "+f"(c[3])
        : "r"(a[0]), "r"(a[1]), "r"(a[2]), "r"(a[3]), "r"(b0), "r"(b1));
}

__device__ __forceinline__ void cp16(float* dst_smem, const float* src) {
    unsigned d = (unsigned)__cvta_generic_to_shared(dst_smem);
    asm volatile("cp.async.cg.shared.global [%0], [%1], 16;" :: "r"(d), "l"(src));
}
#define CP_COMMIT() asm volatile("cp.async.commit_group;")
#define CP_WAIT0()  asm volatile("cp.async.wait_group 0;")

// ---------------------------------------------------------------------------
// Phase 1: h = x @ W^T + b ; writes g_hn = tf32(h/||h||) row-major and
// g_ht = tf32(h) transposed [B][D][N]. Grid: 128 CTAs x 256 thr, 128 rows/CTA.
// ---------------------------------------------------------------------------
__global__ __launch_bounds__(256, 1)
void linear_norm_kernel(const float* __restrict__ x, const float* __restrict__ W,
                        const float* __restrict__ bias) {
    extern __shared__ float sm[];
    float* sX = sm;              // [128][132]
    float* sW = sm + 128 * 132;  // [128][132]
    const int tid = threadIdx.x, lane = tid & 31, wid = tid >> 5;
    const int g = lane >> 2, q = lane & 3, wm = wid * 16;
    const int r0 = blockIdx.x * 128;
    const int b  = r0 >> 11;          // batch index
    const int n0 = r0 & (NN - 1);     // row offset within batch

    for (int i = tid; i < 128 * 32; i += 256) {
        int r = i >> 5, c = (i & 31) * 4;
        float4 v = *(const float4*)(x + (size_t)(r0 + r) * 128 + c);
        float* d = sX + r * 132 + c;
        d[0] = to_tf32(v.x); d[1] = to_tf32(v.y); d[2] = to_tf32(v.z); d[3] = to_tf32(v.w);
        float4 w = *(const float4*)(W + (size_t)r * 128 + c);
        float* dw = sW + r * 132 + c;
        dw[0] = to_tf32(w.x); dw[1] = to_tf32(w.y); dw[2] = to_tf32(w.z); dw[3] = to_tf32(w.w);
    }
    __syncthreads();

    float acc[16][4];
#pragma unroll
    for (int nf = 0; nf < 16; nf++) { acc[nf][0] = acc[nf][1] = acc[nf][2] = acc[nf][3] = 0.f; }

#pragma unroll
    for (int ks = 0; ks < 16; ks++) {
        const int k0 = ks * 8;
        const float* ar = sX + (wm + g) * 132;
        unsigned a[4];
        a[0] = fbits(ar[k0 + q]);             a[1] = fbits(ar[8 * 132 + k0 + q]);
        a[2] = fbits(ar[k0 + q + 4]);         a[3] = fbits(ar[8 * 132 + k0 + q + 4]);
#pragma unroll
        for (int nf = 0; nf < 16; nf++) {
            const float* br = sW + (nf * 8 + g) * 132;
            mma8(acc[nf], a, fbits(br[k0 + q]), fbits(br[k0 + q + 4]));
        }
    }

    // bias + row-wise squared-norm (quad reduce: lanes sharing g)
    float s0 = 0.f, s1 = 0.f;
#pragma unroll
    for (int nf = 0; nf < 16; nf++) {
        int c = nf * 8 + 2 * q;
        float b0 = bias[c], b1 = bias[c + 1];
        acc[nf][0] += b0; acc[nf][1] += b1; acc[nf][2] += b0; acc[nf][3] += b1;
        s0 += acc[nf][0] * acc[nf][0] + acc[nf][1] * acc[nf][1];
        s1 += acc[nf][2] * acc[nf][2] + acc[nf][3] * acc[nf][3];
    }
    s0 += __shfl_xor_sync(0xffffffffu, s0, 1);
    s0 += __shfl_xor_sync(0xffffffffu, s0, 2);
    s1 += __shfl_xor_sync(0xffffffffu, s1, 1);
    s1 += __shfl_xor_sync(0xffffffffu, s1, 2);
    const float inv0 = 1.f / fmaxf(sqrtf(s0), 1e-12f);
    const float inv1 = 1.f / fmaxf(sqrtf(s1), 1e-12f);

    // g_hn row-major (tf32-rounded)
    const size_t row0 = (size_t)(r0 + wm + g) * 128;
    const size_t row1 = (size_t)(r0 + wm + g + 8) * 128;
#pragma unroll
    for (int nf = 0; nf < 16; nf++) {
        int c = nf * 8 + 2 * q;
        *(float2*)(g_hn + row0 + c) = make_float2(to_tf32(acc[nf][0] * inv0), to_tf32(acc[nf][1] * inv0));
        *(float2*)(g_hn + row1 + c) = make_float2(to_tf32(acc[nf][2] * inv1), to_tf32(acc[nf][3] * inv1));
    }

    // g_ht: route through smem transpose (reuse sX/sW region; conflict-free:
    // bank = 8q + g + 16*wid mod 32, a permutation of 0..31 per warp)
    __syncthreads();                 // all warps done reading sX/sW
    float* sT = sm;                  // [128 d][132]
#pragma unroll
    for (int nf = 0; nf < 16; nf++) {
        int c = nf * 8 + 2 * q;
        sT[(c + 0) * 132 + wm + g]     = to_tf32(acc[nf][0]);
        sT[(c + 1) * 132 + wm + g]     = to_tf32(acc[nf][1]);
        sT[(c + 0) * 132 + wm + g + 8] = to_tf32(acc[nf][2]);
        sT[(c + 1) * 132 + wm + g + 8] = to_tf32(acc[nf][3]);
    }
    __syncthreads();
    float* dstb = g_ht + (size_t)b * DD * NN;
    for (int i = tid; i < 128 * 32; i += 256) {
        int d = i >> 5, c4 = (i & 31) * 4;
        float4 v = *(const float4*)(sT + d * 132 + c4);
        *(float4*)(dstb + (size_t)d * NN + n0 + c4) = v;
    }
}

// ---------------------------------------------------------------------------
// Phase 2: per (p-tile, batch) CTA, flash-style over q-tiles of 64:
//   S = HNp @ HNq^T ; S *= EW ; ACC += tf32(S) @ Hq
// cp.async double-buffered q-tiles; GEMM1 A-fragments register-resident;
// edge_weight read exactly once, prefetched into registers.
// GEMM1 warp tile: m16 x n64 (wm = wid*16).
// GEMM2 warp tile: m32 x n64 (wm2 = (wid&3)*32, nc = (wid>>2)*64).
// Grid: (16, 8) x 256 threads. 172 KB dynamic smem.
// ---------------------------------------------------------------------------
__global__ __launch_bounds__(256, 1)
void aggregate_kernel(const float* __restrict__ ew, float* __restrict__ out) {
    extern __shared__ float sm[];
    // double-buffered tiles
    float* sHN0 = sm;                    // [64][132]  hn q-tile  (GEMM1 B)
    float* sHN1 = sHN0 + 64 * 132;
    float* sHT0 = sHN1 + 64 * 132;       // [128 d][68] h q-tile  (GEMM2 B)
    float* sHT1 = sHT0 + 128 * 68;
    float* sS   = sHT1 + 128 * 68;       // [128][68]  gated scores (GEMM2 A)

    const int tid = threadIdx.x, lane = tid & 31, wid = tid >> 5;
    const int g = lane >> 2, q = lane & 3;
    const int wm  = wid * 16;            // GEMM1 m-offset (also sS write rows)
    const int wm2 = (wid & 3) * 32;      // GEMM2 m-offset
    const int nc  = (wid >> 2) * 64;     // GEMM2 n-offset
    const int m0 = blockIdx.x * 128;
    const int b = blockIdx.y;
    const float* hn = g_hn + (size_t)b * NN * DD;
    const float* ht = g_ht + (size_t)b * DD * NN;

    // --- issue cp.async for tile 0 ---
    {
        const float* srcn = hn;                        // q0 = 0
#pragma unroll
        for (int t = 0; t < 8; t++) {                  // sHN: 64 rows x 32 chunks
            int idx = tid + t * 256;
            int r = idx >> 5, ck = (idx & 31) * 4;
            cp16(sHN0 + r * 132 + ck, srcn + (size_t)r * 128 + ck);
        }
#pragma unroll
        for (int t = 0; t < 8; t++) {                  // sHT: 128 rows x 16 chunks
            int idx = tid + t * 256;
            int d = idx >> 4, ck = (idx & 15) * 4;
            cp16(sHT0 + d * 68 + ck, ht + (size_t)d * NN + ck);
        }
        CP_COMMIT();
    }

    // --- GEMM1 A-fragments (hn p-tile rows) -> registers, one-time ---
    unsigned aF[16][4];
    {
        const float* ar0 = hn + (size_t)(m0 + wm + g) * 128;
        const float* ar1 = ar0 + 8 * 128;
#pragma unroll
        for (int ks = 0; ks < 16; ks++) {
            int k0 = ks * 8;
            aF[ks][0] = fbits(ar0[k0 + q]);
            aF[ks][1] = fbits(ar1[k0 + q]);
            aF[ks][2] = fbits(ar0[k0 + q + 4]);
            aF[ks][3] = fbits(ar1[k0 + q + 4]);
        }
    }

    float acc[2][8][4];
#pragma unroll
    for (int mt = 0; mt < 2; mt++)
#pragma unroll
        for (int nf = 0; nf < 8; nf++) {
            acc[mt][nf][0] = acc[mt][nf][1] = acc[mt][nf][2] = acc[mt][nf][3] = 0.f;
        }

    const float* e0base = ew + ((size_t)b * NN + (m0 + wm + g)) * NN;
    const float* e1base = e0base + 8 * NN;
    float* ss0 = sS + (wm + g) * 68;
    float* ss1 = sS + (wm + g + 8) * 68;
    // GEMM2 A-fragment source rows (cross-warp, read after __syncthreads)
    const float* sr0 = sS + (wm2 + g) * 68;
    const float* sr1 = sS + (wm2 + g + 8) * 68;
    const float* sr2 = sS + (wm2 + 16 + g) * 68;
    const float* sr3 = sS + (wm2 + 24 + g) * 68;

    for (int it = 0; it < 32; it++) {
        const int q0 = it * 64;
        float* bHN = (it & 1) ? sHN1 : sHN0;
        float* bHT = (it & 1) ? sHT1 : sHT0;

        CP_WAIT0();
        __syncthreads();   // tile `it` visible to all; prev iter's sS reads done

        // prefetch edge_weight tile into registers (hides DRAM latency under GEMM1)
        float2 e0[8], e1[8];
#pragma unroll
        for (int nf = 0; nf < 8; nf++) {
            int c = nf * 8 + 2 * q;
            e0[nf] = *(const float2*)(e0base + q0 + c);
            e1[nf] = *(const float2*)(e1base + q0 + c);
        }

        // issue cp.async for tile it+1 into the other buffer (post-sync: safe —
        // every warp has finished reading that buffer's previous contents)
        if (it < 31) {
            float* nHN = (it & 1) ? sHN0 : sHN1;
            float* nHT = (it & 1) ? sHT0 : sHT1;
            const float* srcn = hn + (size_t)(q0 + 64) * 128;
            const float* srct = ht + (q0 + 64);
#pragma unroll
            for (int t = 0; t < 8; t++) {
                int idx = tid + t * 256;
                int r = idx >> 5, ck = (idx & 31) * 4;
                cp16(nHN + r * 132 + ck, srcn + (size_t)r * 128 + ck);
            }
#pragma unroll
            for (int t = 0; t < 8; t++) {
                int idx = tid + t * 256;
                int d = idx >> 4, ck = (idx & 15) * 4;
                cp16(nHT + d * 68 + ck, srct + (size_t)d * NN + ck);
            }
            CP_COMMIT();
        }

        // GEMM1: S(16x64 per warp) = HNp @ HNq^T
        float s[8][4];
#pragma unroll
        for (int nf = 0; nf < 8; nf++) { s[nf][0] = s[nf][1] = s[nf][2] = s[nf][3] = 0.f; }
#pragma unroll
        for (int ks = 0; ks < 16; ks++) {
            const int k0 = ks * 8;
#pragma unroll
            for (int nf = 0; nf < 8; nf++) {
                const float* br = bHN + (nf * 8 + g) * 132;
                mma8(s[nf], aF[ks], fbits(br[k0 + q]), fbits(br[k0 + q + 4]));
            }
        }

        // gate by edge_weight, tf32-round, park in sS (explicit STS.64 pairs)
#pragma unroll
        for (int nf = 0; nf < 8; nf++) {
            int c = nf * 8 + 2 * q;
            *(float2*)(ss0 + c) = make_float2(to_tf32(s[nf][0] * e0[nf].x),
                                              to_tf32(s[nf][1] * e0[nf].y));
            *(float2*)(ss1 + c) = make_float2(to_tf32(s[nf][2] * e1[nf].x),
                                              to_tf32(s[nf][3] * e1[nf].y));
        }
        __syncthreads();   // S rows consumed cross-warp in GEMM2

        // GEMM2: ACC(m32 x n64 per warp) += S @ Hq
#pragma unroll
        for (int ks = 0; ks < 8; ks++) {
            const int k0 = ks * 8;
            unsigned a0[4], a1[4];
            a0[0] = fbits(sr0[k0 + q]);     a0[1] = fbits(sr1[k0 + q]);
            a0[2] = fbits(sr0[k0 + q + 4]); a0[3] = fbits(sr1[k0 + q + 4]);
            a1[0] = fbits(sr2[k0 + q]);     a1[1] = fbits(sr3[k0 + q]);
            a1[2] = fbits(sr2[k0 + q + 4]); a1[3] = fbits(sr3[k0 + q + 4]);
#pragma unroll
            for (int nf = 0; nf < 8; nf++) {
                const float* br = bHT + (nc + nf * 8 + g) * 68;
                unsigned b0 = fbits(br[k0 + q]);
                unsigned b1 = fbits(br[k0 + q + 4]);
                mma8(acc[0][nf], a0, b0, b1);
                mma8(acc[1][nf], a1, b0, b1);
            }
        }
    }

    // ReLU + store (GEMM2 tiling: rows wm2+mt*16+{g,g+8}, cols nc+nf*8+2q)
#pragma unroll
    for (int mt = 0; mt < 2; mt++) {
        float* o0 = out + ((size_t)b * NN + (m0 + wm2 + mt * 16 + g)) * DD;
        float* o1 = o0 + 8 * DD;
#pragma unroll
        for (int nf = 0; nf < 8; nf++) {
            int c = nc + nf * 8 + 2 * q;
            *(float2*)(o0 + c) = make_float2(fmaxf(acc[mt][nf][0], 0.f), fmaxf(acc[mt][nf][1], 0.f));
            *(float2*)(o1 + c) = make_float2(fmaxf(acc[mt][nf][2], 0.f), fmaxf(acc[mt][nf][3], 0.f));
        }
    }
}

extern "C" void kernel_launch(void* const* d_in, const int* in_sizes, int n_in,
                              void* d_out, int out_size) {
    const float* x    = (const float*)d_in[0];
    const float* ew   = (const float*)d_in[1];
    const float* W    = (const float*)d_in[2];
    const float* bias = (const float*)d_in[3];
    float* out = (float*)d_out;

    const int smem1 = 2 * 128 * 132 * (int)sizeof(float);                            // 135168
    const int smem2 = (2 * 64 * 132 + 2 * 128 * 68 + 128 * 68) * (int)sizeof(float); // 172032
    cudaFuncSetAttribute(linear_norm_kernel, cudaFuncAttributeMaxDynamicSharedMemorySize, smem1);
    cudaFuncSetAttribute(aggregate_kernel, cudaFuncAttributeMaxDynamicSharedMemorySize, smem2);

    linear_norm_kernel<<<128, 256, smem1>>>(x, W, bias);
    dim3 grid2(16, 8);
    aggregate_kernel<<<grid2, 256, smem2>>>(ew, out);
}